// round 2
// baseline (speedup 1.0000x reference)
#include <cuda_runtime.h>

#define GS 32
#define G3 (GS * GS * GS)
#define NPTS 4096
#define NBATCH 256

// Scratch: 6 affine transforms (9 matrix + 3 translation floats) + 2 double accumulators.
__device__ float  g_xf[6][12];
__device__ double g_acc[2];

// ---------------------------------------------------------------------------
// Setup: fold plane reflections and quaternion rotations into affine maps,
// and zero the accumulators (must happen every graph replay).
// ---------------------------------------------------------------------------
__global__ void setup_kernel(const float* __restrict__ plane,
                             const float* __restrict__ quat) {
    if (threadIdx.x != 0) return;
    g_acc[0] = 0.0;
    g_acc[1] = 0.0;

    // Plane reflections: x' = x - 2*((x.n + d)/|n|^2) n  =>  A = I - (2/s) n n^T, b = -(2d/s) n
    for (int i = 0; i < 3; i++) {
        float nx = plane[i * 4 + 0], ny = plane[i * 4 + 1];
        float nz = plane[i * 4 + 2], d  = plane[i * 4 + 3];
        float s   = nx * nx + ny * ny + nz * nz;
        float inv = 2.0f / s;
        float* A = g_xf[i];
        A[0] = 1.f - inv * nx * nx; A[1] =      -inv * nx * ny; A[2] =      -inv * nx * nz;
        A[3] =      -inv * ny * nx; A[4] = 1.f - inv * ny * ny; A[5] =      -inv * ny * nz;
        A[6] =      -inv * nz * nx; A[7] =      -inv * nz * ny; A[8] = 1.f - inv * nz * nz;
        A[9]  = -inv * d * nx;
        A[10] = -inv * d * ny;
        A[11] = -inv * d * nz;
    }

    // Quaternion rotations -> standard rotation matrix (unit quaternion).
    for (int i = 0; i < 3; i++) {
        float q0 = quat[i * 4 + 0], q1 = quat[i * 4 + 1];
        float q2 = quat[i * 4 + 2], q3 = quat[i * 4 + 3];
        float nrm = sqrtf(q0 * q0 + q1 * q1 + q2 * q2 + q3 * q3);
        float w = q0 / nrm, x = q1 / nrm, y = q2 / nrm, z = q3 / nrm;
        float* A = g_xf[3 + i];
        A[0] = 1.f - 2.f * (y * y + z * z);
        A[1] = 2.f * (x * y - w * z);
        A[2] = 2.f * (x * z + w * y);
        A[3] = 2.f * (x * y + w * z);
        A[4] = 1.f - 2.f * (x * x + z * z);
        A[5] = 2.f * (y * z - w * x);
        A[6] = 2.f * (x * z - w * y);
        A[7] = 2.f * (y * z + w * x);
        A[8] = 1.f - 2.f * (x * x + y * y);
        A[9] = A[10] = A[11] = 0.f;
    }
}

// ---------------------------------------------------------------------------
// Main loss kernel. Grid = (8, NBATCH): the 8 CTAs of a batch co-run so the
// 512 KB per-batch cp/voxel slice stays L2-resident while being gathered.
//
// Per point, three explicit phases to maximize memory-level parallelism:
//   phase 1: all 6 affine transforms + flattened indices (pure FMA/ALU)
//   phase 2: all 6 voxel LDGs issued back-to-back (MLP=6)
//   phase 3: conditional cp gathers + distance accumulate
// ---------------------------------------------------------------------------
__global__ void __launch_bounds__(256)
loss_kernel(const float* __restrict__ points,
            const float* __restrict__ cp,
            const float* __restrict__ voxel) {
    __shared__ float xf[72];
    __shared__ float red[2][8];

    int tid = threadIdx.x;
    if (tid < 72) xf[tid] = ((const float*)g_xf)[tid];
    __syncthreads();

    int b = blockIdx.y;
    const float* pb  = points + (size_t)b * NPTS * 3;
    const float* cpb = cp     + (size_t)b * G3 * 3;
    const float* vb  = voxel  + (size_t)b * G3;

    const float gm = -0.484375f;  // grid_min = -0.5 + 0.5/32 (exact in fp32)

    float aR = 0.f, aQ = 0.f;

    for (int n = blockIdx.x * blockDim.x + tid; n < NPTS; n += blockDim.x * gridDim.x) {
        float px = pb[n * 3 + 0];
        float py = pb[n * 3 + 1];
        float pz = pb[n * 3 + 2];

        float tx6[6], ty6[6], tz6[6];
        int   idx6[6];

        // ---- phase 1: transforms + indices (no memory dependence) ----
#pragma unroll
        for (int t = 0; t < 6; t++) {
            const float* A = &xf[t * 12];
            float tx = fmaf(A[0], px, fmaf(A[1], py, fmaf(A[2], pz, A[9])));
            float ty = fmaf(A[3], px, fmaf(A[4], py, fmaf(A[5], pz, A[10])));
            float tz = fmaf(A[6], px, fmaf(A[7], py, fmaf(A[8], pz, A[11])));
            tx6[t] = tx; ty6[t] = ty; tz6[t] = tz;

            // inds = (x - grid_min)*32 ; clip [0,31] ; round-half-even (rintf == jnp.round)
            float fx = rintf(fminf(fmaxf((tx - gm) * 32.f, 0.f), 31.f));
            float fy = rintf(fminf(fmaxf((ty - gm) * 32.f, 0.f), 31.f));
            float fz = rintf(fminf(fmaxf((tz - gm) * 32.f, 0.f), 31.f));
            // fx*1024+fy*32+fz <= 32767: exact in fp32 -> single float->int convert
            idx6[t] = (int)fmaf(fx, 1024.f, fmaf(fy, 32.f, fz));
        }

        // ---- phase 2: all voxel loads in flight together (MLP=6) ----
        float v6[6];
#pragma unroll
        for (int t = 0; t < 6; t++) v6[t] = __ldg(vb + idx6[t]);

        // ---- phase 3: conditional cp gathers + accumulate ----
        // voxel is exactly 0.0 or 1.0; mask=(1-v)^2 in {0,1}. v==1 -> zero
        // contribution -> skip the 12B cp gather (~20% of evals).
#pragma unroll
        for (int t = 0; t < 6; t++) {
            if (v6[t] == 0.f) {
                const float* c = cpb + (size_t)idx6[t] * 3;
                float dx = tx6[t] - __ldg(c + 0);
                float dy = ty6[t] - __ldg(c + 1);
                float dz = tz6[t] - __ldg(c + 2);
                float sq = fmaf(dx, dx, fmaf(dy, dy, dz * dz));
                if (t < 3) aR += sq; else aQ += sq;
            }
        }
    }

    // Warp reduce, block reduce, one double atomic per block per loss.
#pragma unroll
    for (int o = 16; o > 0; o >>= 1) {
        aR += __shfl_down_sync(0xffffffffu, aR, o);
        aQ += __shfl_down_sync(0xffffffffu, aQ, o);
    }
    int lane = tid & 31, w = tid >> 5;
    if (lane == 0) { red[0][w] = aR; red[1][w] = aQ; }
    __syncthreads();
    if (tid == 0) {
        float sR = 0.f, sQ = 0.f;
#pragma unroll
        for (int i = 0; i < 8; i++) { sR += red[0][i]; sQ += red[1][i]; }
        atomicAdd(&g_acc[0], (double)sR);
        atomicAdd(&g_acc[1], (double)sQ);
    }
}

// ---------------------------------------------------------------------------
// Finalize: loss = (sum over all batches) / NBATCH  (mean over batch axis).
// ---------------------------------------------------------------------------
__global__ void final_kernel(float* __restrict__ out) {
    if (threadIdx.x == 0) {
        out[0] = (float)(g_acc[0] / (double)NBATCH);
        out[1] = (float)(g_acc[1] / (double)NBATCH);
    }
}

extern "C" void kernel_launch(void* const* d_in, const int* in_sizes, int n_in,
                              void* d_out, int out_size) {
    const float* points = (const float*)d_in[0];
    const float* cp     = (const float*)d_in[1];
    const float* voxel  = (const float*)d_in[2];
    const float* plane  = (const float*)d_in[3];
    const float* quat   = (const float*)d_in[4];

    setup_kernel<<<1, 32>>>(plane, quat);

    dim3 grid(8, NBATCH);          // 2048 CTAs; 2 points/thread
    loss_kernel<<<grid, 256>>>(points, cp, voxel);

    final_kernel<<<1, 32>>>((float*)d_out);
}